// round 12
// baseline (speedup 1.0000x reference)
#include <cuda_runtime.h>
#include <stdint.h>

#define NMAX 100000
#define EMAX 1000000
#define D 64
#define NSCANMAX 128   // >= ceil(NMAX/1024)

typedef unsigned long long u64;

// ---------------- scratch (device globals; ~61 MB) ----------------
__device__ __align__(16) float g_a[NMAX * D];  // aggregation output (fp32)
__device__ __align__(16) float g_y[NMAX * D];  // y = dinv*x, then dinv*x1 (fp32)
__device__ float g_dinv[NMAX];
__device__ int   g_deg [NMAX];        // statically 0; k_scan re-zeroes after reading
__device__ int   g_ptr [NMAX];
__device__ int   g_cur [NMAX];
__device__ int   g_src [2 * EMAX];    // CSR: src node only (weights folded into y)
__device__ int   g_scanstat[NSCANMAX];
__device__ int   g_ticket;
// Static init = 1 (int64 assumed). Only ever cleared (idempotent across replays).
__device__ int   g_is64 = 1;

// ---------------- f32x2 packed helpers ----------------
__device__ __forceinline__ u64 pk2(float a, float b) {
    u64 r; asm("mov.b64 %0, {%1, %2};" : "=l"(r) : "f"(a), "f"(b)); return r;
}
__device__ __forceinline__ u64 fma2(u64 a, u64 b, u64 c) {
    u64 d; asm("fma.rn.f32x2 %0, %1, %2, %3;" : "=l"(d) : "l"(a), "l"(b), "l"(c)); return d;
}
__device__ __forceinline__ u64 add2(u64 a, u64 b) {
    u64 d; asm("add.rn.f32x2 %0, %1, %2;" : "=l"(d) : "l"(a), "l"(b)); return d;
}
__device__ __forceinline__ float2 up2(u64 a) {
    float2 f; asm("mov.b64 {%0, %1}, %2;" : "=f"(f.x), "=f"(f.y) : "l"(a)); return f;
}

__device__ __forceinline__ int get_idx(const void* ei, int i) {
    if (g_is64) return (int)((const long long*)ei)[i];
    return ((const int*)ei)[i];
}

// Bounded dtype sniff: odd 32-bit words of the first min(256, half) logical entries
// (words < 512: in-bounds under BOTH layouts). int64 high words are 0 for node ids.
__device__ __forceinline__ int detect_is32(const int* __restrict__ w32, int twoE,
                                           int* sh_flag) {
    if (threadIdx.x == 0) *sh_flag = 0;
    __syncthreads();
    int lim = twoE >> 1; if (lim > 256) lim = 256;
    if ((int)threadIdx.x < lim && w32[2 * threadIdx.x + 1] != 0) *sh_flag = 1;
    __syncthreads();
    return *sh_flag;
}

// ---- launch 0 (grid-split): [0,NB) normalize x -> out ; [NB,..) degree count ----
__global__ void k_prepcount(const float* __restrict__ emb, const int* __restrict__ w32,
                            float* __restrict__ out, int N, int twoE, int NB) {
    __shared__ int sh_is32;
    int b = blockIdx.x;
    if (b < NB) {
        int gtid = b * blockDim.x + threadIdx.x;
        int warp = gtid >> 5, lane = gtid & 31;
        if (warp < N) {
            float2 v = ((const float2*)(emb + (size_t)warp * D))[lane];
            float s = v.x * v.x + v.y * v.y;
            #pragma unroll
            for (int o = 16; o; o >>= 1) s += __shfl_xor_sync(0xFFFFFFFFu, s, o);
            float inv = 1.0f / fmaxf(sqrtf(s), 1e-12f);
            ((float2*)(out + (size_t)warp * D))[lane] = make_float2(v.x * inv, v.y * inv);
        }
        if (gtid < NSCANMAX) g_scanstat[gtid] = 0;
        if (gtid == 0) g_ticket = 0;
    } else {
        int is32 = detect_is32(w32, twoE, &sh_is32);
        if (is32 && threadIdx.x == 0) g_is64 = 0;      // publish for k_place
        int i = (b - NB) * blockDim.x + threadIdx.x;   // logical entry index
        if (i < twoE) {
            int u = is32 ? w32[i] : (int)((const long long*)w32)[i];
            if ((unsigned)u < (unsigned)N) atomicAdd(&g_deg[u], 1);
        }
    }
}

// ---- single-pass decoupled-lookback scan of deg; dinv = rsqrt(cnt+1); self-clean ----
__global__ void k_scan(int N) {
    __shared__ int s[1024];
    __shared__ int sh_vbid, sh_run;
    int tid = threadIdx.x;
    if (tid == 0) sh_vbid = atomicAdd(&g_ticket, 1);
    __syncthreads();
    int vbid = sh_vbid;
    int i = vbid * 1024 + tid;

    int v = 0;
    if (i < N) {
        v = g_deg[i];
        g_deg[i] = 0;                                   // ready for next replay
        g_dinv[i] = rsqrtf((float)(v + 1));             // +1 = self loop
    }
    s[tid] = v;
    __syncthreads();
    for (int off = 1; off < 1024; off <<= 1) {
        int t = (tid >= off) ? s[tid - off] : 0;
        __syncthreads();
        s[tid] += t;
        __syncthreads();
    }
    int total = s[1023];
    int ex = s[tid] - v;

    if (tid == 0) {
        if (vbid == 0) {
            atomicExch(&g_scanstat[0], (total << 2) | 2);
            sh_run = 0;
        } else {
            atomicExch(&g_scanstat[vbid], (total << 2) | 1);
            int run = 0, p = vbid - 1;
            while (true) {
                int st = atomicAdd(&g_scanstat[p], 0);
                int f = st & 3;
                if (f == 2) { run += st >> 2; break; }
                if (f == 1) { run += st >> 2; p--; }
            }
            atomicExch(&g_scanstat[vbid], ((run + total) << 2) | 2);
            sh_run = run;
        }
    }
    __syncthreads();
    if (i < N) {
        int p = sh_run + ex;
        g_ptr[i] = p;
        g_cur[i] = p;
    }
}

// ---- launch 2 (grid-split): [0,SB) y = dinv*x (fp32) ; [SB,..) place edges ----
__global__ void k_place(const void* __restrict__ ei, const float* __restrict__ x,
                        int E, int N, int SB) {
    int b = blockIdx.x;
    if (b < SB) {
        int row  = b * 16 + (threadIdx.x >> 4);
        int lane = threadIdx.x & 15;
        if (row >= N) return;
        float di = g_dinv[row];
        float4 v = ((const float4*)(x + (size_t)row * D))[lane];
        v.x *= di; v.y *= di; v.z *= di; v.w *= di;
        ((float4*)(g_y + (size_t)row * D))[lane] = v;
    } else {
        int e = (b - SB) * 256 + threadIdx.x;
        if (e >= E) return;
        int u = get_idx(ei, e);
        int v = get_idx(ei, E + e);
        if ((unsigned)u >= (unsigned)N || (unsigned)v >= (unsigned)N) return;
        int p = atomicAdd(&g_cur[v], 1);
        if ((unsigned)p < 2u * EMAX) g_src[p] = u;
        int q = atomicAdd(&g_cur[u], 1);
        if ((unsigned)q < 2u * EMAX) g_src[q] = v;
    }
}

// ---- aggregation: a[v] = dinv[v] * ( y[v] + sum_u y[u] ) ----
// fp32 features, packed f32x2 adds; 16 lanes/node (2 nodes/warp), 8-edge unroll.
__global__ void k_gather(int N) {
    const float* __restrict__ in = g_y;
    int node = blockIdx.x * 16 + (threadIdx.x >> 4);
    int lane = threadIdx.x & 15;
    if (node >= N) return;

    const ulonglong2* self = (const ulonglong2*)(in + (size_t)node * D);
    ulonglong2 sv = self[lane];
    u64 acc01 = sv.x, acc23 = sv.y;          // y[v] (self-loop term)

    int s0  = g_ptr[node];
    int cnt = g_cur[node] - s0;

    int t = 0;
    for (; t + 8 <= cnt; t += 8) {
        int s[8];
        #pragma unroll
        for (int j = 0; j < 8; j++) s[j] = g_src[s0 + t + j];
        ulonglong2 h[8];
        #pragma unroll
        for (int j = 0; j < 8; j++)
            h[j] = ((const ulonglong2*)(in + (size_t)s[j] * D))[lane];
        #pragma unroll
        for (int j = 0; j < 8; j++) {
            acc01 = add2(acc01, h[j].x);
            acc23 = add2(acc23, h[j].y);
        }
    }
    for (; t < cnt; t++) {
        int ss = g_src[s0 + t];
        ulonglong2 h = ((const ulonglong2*)(in + (size_t)ss * D))[lane];
        acc01 = add2(acc01, h.x);
        acc23 = add2(acc23, h.y);
    }

    float di = g_dinv[node];
    u64 dd = pk2(di, di);
    acc01 = fma2(acc01, dd, pk2(0.f, 0.f));
    acc23 = fma2(acc23, dd, pk2(0.f, 0.f));
    ulonglong2* o = (ulonglong2*)(g_a + (size_t)node * D);
    ulonglong2 ov; ov.x = acc01; ov.y = acc23;
    o[lane] = ov;
}

// ---- GEMM 1 (f32x2): x1 = leaky(a W1^T + b1); out += x1; g_y = dinv*x1 ----
__global__ void k_gemm1(const float* __restrict__ W, const float* __restrict__ b,
                        float* __restrict__ out, int N) {
    __shared__ __align__(16) float s_in[64 * 64];
    __shared__ __align__(16) float s_wt[64 * 64];  // s_wt[k*64+j] = W[j*64+k]

    int tid  = threadIdx.x;
    int base = blockIdx.x * 64;

    const float4* in4  = (const float4*)(g_a + (size_t)base * D);
    float4*       sin4 = (float4*)s_in;
    #pragma unroll
    for (int r = 0; r < 4; r++) {
        int idx4 = tid + 256 * r;
        int row  = idx4 >> 4;
        sin4[idx4] = (base + row < N) ? in4[idx4] : make_float4(0.f,0.f,0.f,0.f);
    }
    #pragma unroll
    for (int r = 0; r < 16; r++) {
        int idx = tid + 256 * r;
        s_wt[(idx >> 6) * 64 + (idx & 63)] = W[(idx & 63) * 64 + (idx >> 6)];
    }
    __syncthreads();

    int ng = tid >> 4, cg = tid & 15;
    int r0 = ng * 4;
    u64 acc[4][2] = {{0,0},{0,0},{0,0},{0,0}};
    const ulonglong2* wt2 = (const ulonglong2*)s_wt;
    #pragma unroll
    for (int k = 0; k < 64; k++) {
        ulonglong2 wv = wt2[k * 16 + cg];
        #pragma unroll
        for (int r = 0; r < 4; r++) {
            float x = s_in[(r0 + r) * 64 + k];
            u64 xx = pk2(x, x);
            acc[r][0] = fma2(xx, wv.x, acc[r][0]);
            acc[r][1] = fma2(xx, wv.y, acc[r][1]);
        }
    }

    float4 bb = ((const float4*)b)[cg];
    #pragma unroll
    for (int r = 0; r < 4; r++) {
        int row = base + r0 + r;
        if (row >= N) break;
        float2 c01 = up2(acc[r][0]);
        float2 c23 = up2(acc[r][1]);
        float4 v = make_float4(c01.x + bb.x, c01.y + bb.y, c23.x + bb.z, c23.y + bb.w);
        v.x = v.x > 0.f ? v.x : 0.01f*v.x; v.y = v.y > 0.f ? v.y : 0.01f*v.y;
        v.z = v.z > 0.f ? v.z : 0.01f*v.z; v.w = v.w > 0.f ? v.w : 0.01f*v.w;
        float di = g_dinv[row];
        ((float4*)(g_y + (size_t)row * D))[cg] =
            make_float4(di * v.x, di * v.y, di * v.z, di * v.w);
        size_t o = (size_t)row * 16 + cg;
        float4 ov = ((const float4*)out)[o];     // holds x
        ov.x += v.x; ov.y += v.y; ov.z += v.z; ov.w += v.w;
        ((float4*)out)[o] = ov;
    }
}

// ---- GEMM 2+3 fused (f32x2): out += leaky(a W2^T + b2) + (a W3^T + b3) ----
__global__ void k_gemm23(const float* __restrict__ W2, const float* __restrict__ b2,
                         const float* __restrict__ W3, const float* __restrict__ b3,
                         float* __restrict__ out, int N) {
    __shared__ __align__(16) float s_in[64 * 64];
    __shared__ __align__(16) float s_w2[64 * 64];
    __shared__ __align__(16) float s_w3[64 * 64];

    int tid  = threadIdx.x;
    int base = blockIdx.x * 64;

    const float4* in4  = (const float4*)(g_a + (size_t)base * D);
    float4*       sin4 = (float4*)s_in;
    #pragma unroll
    for (int r = 0; r < 4; r++) {
        int idx4 = tid + 256 * r;
        int row  = idx4 >> 4;
        sin4[idx4] = (base + row < N) ? in4[idx4] : make_float4(0.f,0.f,0.f,0.f);
    }
    #pragma unroll
    for (int r = 0; r < 16; r++) {
        int idx = tid + 256 * r;
        int j = idx & 63, k = idx >> 6;
        s_w2[k * 64 + j] = W2[j * 64 + k];
        s_w3[k * 64 + j] = W3[j * 64 + k];
    }
    __syncthreads();

    int ng = tid >> 4, cg = tid & 15;
    int r0 = ng * 4;
    u64 p[4][2] = {{0,0},{0,0},{0,0},{0,0}};
    u64 q[4][2] = {{0,0},{0,0},{0,0},{0,0}};
    const ulonglong2* w22 = (const ulonglong2*)s_w2;
    const ulonglong2* w32 = (const ulonglong2*)s_w3;
    #pragma unroll
    for (int k = 0; k < 64; k++) {
        ulonglong2 u2 = w22[k * 16 + cg];
        ulonglong2 v2 = w32[k * 16 + cg];
        #pragma unroll
        for (int r = 0; r < 4; r++) {
            float x = s_in[(r0 + r) * 64 + k];
            u64 xx = pk2(x, x);
            p[r][0] = fma2(xx, u2.x, p[r][0]);
            p[r][1] = fma2(xx, u2.y, p[r][1]);
            q[r][0] = fma2(xx, v2.x, q[r][0]);
            q[r][1] = fma2(xx, v2.y, q[r][1]);
        }
    }

    float4 bb2 = ((const float4*)b2)[cg];
    float4 bb3 = ((const float4*)b3)[cg];
    #pragma unroll
    for (int r = 0; r < 4; r++) {
        int row = base + r0 + r;
        if (row >= N) break;
        float2 p01 = up2(p[r][0]), p23 = up2(p[r][1]);
        float2 q01 = up2(q[r][0]), q23 = up2(q[r][1]);
        float4 pv = make_float4(p01.x + bb2.x, p01.y + bb2.y, p23.x + bb2.z, p23.y + bb2.w);
        pv.x = pv.x > 0.f ? pv.x : 0.01f*pv.x; pv.y = pv.y > 0.f ? pv.y : 0.01f*pv.y;
        pv.z = pv.z > 0.f ? pv.z : 0.01f*pv.z; pv.w = pv.w > 0.f ? pv.w : 0.01f*pv.w;
        float4 qv = make_float4(q01.x + bb3.x, q01.y + bb3.y, q23.x + bb3.z, q23.y + bb3.w);
        size_t o = (size_t)row * 16 + cg;
        float4 ov = ((const float4*)out)[o];     // holds x + x1
        ov.x += pv.x + qv.x;
        ov.y += pv.y + qv.y;
        ov.z += pv.z + qv.z;
        ov.w += pv.w + qv.w;
        ((float4*)out)[o] = ov;
    }
}

// ---------------- launch ----------------
extern "C" void kernel_launch(void* const* d_in, const int* in_sizes, int n_in,
                              void* d_out, int out_size) {
    const void*  ei  = d_in[0];
    const float* emb = (const float*)d_in[1];
    const float* W1 = (const float*)d_in[2];
    const float* b1 = (const float*)d_in[3];
    const float* W2 = (const float*)d_in[4];
    const float* b2 = (const float*)d_in[5];
    const float* W3 = (const float*)d_in[6];
    const float* b3 = (const float*)d_in[7];
    float* out = (float*)d_out;

    int E = in_sizes[0] / 2;
    int N = in_sizes[1] / D;

    int NB = (N * 32 + 255) / 256;                // normalize blocks (warp/node)
    int CB = (2 * E + 255) / 256;                 // count blocks
    k_prepcount<<<NB + CB, 256>>>(emb, (const int*)ei, out, N, 2 * E, NB);

    int B = (N + 1023) / 1024;
    k_scan<<<B, 1024>>>(N);

    int SB = (N + 15) / 16;                       // scale blocks (16 rows / block)
    int PB = (E + 255) / 256;                     // place blocks
    k_place<<<SB + PB, 256>>>(ei, out, E, N, SB);

    int gb = (N + 63) / 64;   // gemm blocks
    int hb = (N + 15) / 16;   // gather blocks (16 nodes / 256-thread block)

    k_gather<<<hb, 256>>>(N);   // launch index 3 — ncu samples this
    k_gemm1 <<<gb, 256>>>(W1, b1, out, N);
    k_gather<<<hb, 256>>>(N);
    k_gemm23<<<gb, 256>>>(W2, b2, W3, b3, out, N);
}

// round 13
// speedup vs baseline: 1.1010x; 1.1010x over previous
#include <cuda_runtime.h>
#include <cuda_bf16.h>
#include <stdint.h>

#define NMAX 100000
#define EMAX 1000000
#define D 64
#define NSCANMAX 128   // >= ceil(NMAX/1024)

typedef unsigned long long u64;

// ---------------- scratch (device globals; ~48 MB) ----------------
__device__ __align__(16) float         g_a[NMAX * D];  // aggregation output (fp32)
__device__ __align__(16) __nv_bfloat16 g_b[NMAX * D];  // bf16 y = dinv*x, then dinv*x1
__device__ float g_dinv[NMAX];
__device__ int   g_deg [NMAX];        // statically 0; k_scan re-zeroes after reading
__device__ int   g_ptr [NMAX];
__device__ int   g_cur [NMAX];
__device__ int   g_src [2 * EMAX];    // CSR: src node only (weights folded into y)
__device__ int   g_scanstat[NSCANMAX];
__device__ int   g_ticket;
// Static init = 1 (int64 assumed). Only ever cleared (idempotent across replays).
__device__ int   g_is64 = 1;

// ---------------- f32x2 packed helpers ----------------
__device__ __forceinline__ u64 pk2(float a, float b) {
    u64 r; asm("mov.b64 %0, {%1, %2};" : "=l"(r) : "f"(a), "f"(b)); return r;
}
__device__ __forceinline__ u64 fma2(u64 a, u64 b, u64 c) {
    u64 d; asm("fma.rn.f32x2 %0, %1, %2, %3;" : "=l"(d) : "l"(a), "l"(b), "l"(c)); return d;
}
__device__ __forceinline__ u64 add2(u64 a, u64 b) {
    u64 d; asm("add.rn.f32x2 %0, %1, %2;" : "=l"(d) : "l"(a), "l"(b)); return d;
}
__device__ __forceinline__ u64 mul2(u64 a, u64 b) {
    u64 d; asm("mul.rn.f32x2 %0, %1, %2;" : "=l"(d) : "l"(a), "l"(b)); return d;
}
__device__ __forceinline__ float2 up2(u64 a) {
    float2 f; asm("mov.b64 {%0, %1}, %2;" : "=f"(f.x), "=f"(f.y) : "l"(a)); return f;
}
// bf16x2 word -> packed f32x2 (exact): lo = w<<16, hi = w & 0xFFFF0000
__device__ __forceinline__ u64 bf2f2(unsigned w) {
    unsigned lo = w << 16;
    unsigned hi = w & 0xFFFF0000u;
    u64 r; asm("mov.b64 %0, {%1, %2};" : "=l"(r) : "r"(lo), "r"(hi));
    return r;
}

__device__ __forceinline__ int get_idx(const void* ei, int i) {
    if (g_is64) return (int)((const long long*)ei)[i];
    return ((const int*)ei)[i];
}

// Bounded dtype sniff: odd 32-bit words of the first min(256, half) logical entries
// (words < 512: in-bounds under BOTH layouts). int64 high words are 0 for node ids.
__device__ __forceinline__ int detect_is32(const int* __restrict__ w32, int twoE,
                                           int* sh_flag) {
    if (threadIdx.x == 0) *sh_flag = 0;
    __syncthreads();
    int lim = twoE >> 1; if (lim > 256) lim = 256;
    if ((int)threadIdx.x < lim && w32[2 * threadIdx.x + 1] != 0) *sh_flag = 1;
    __syncthreads();
    return *sh_flag;
}

// ---- launch 0 (grid-split): [0,NB) normalize x -> out ; [NB,..) degree count ----
__global__ void k_prepcount(const float* __restrict__ emb, const int* __restrict__ w32,
                            float* __restrict__ out, int N, int twoE, int NB) {
    __shared__ int sh_is32;
    int b = blockIdx.x;
    if (b < NB) {
        int gtid = b * blockDim.x + threadIdx.x;
        int warp = gtid >> 5, lane = gtid & 31;
        if (warp < N) {
            float2 v = ((const float2*)(emb + (size_t)warp * D))[lane];
            float s = v.x * v.x + v.y * v.y;
            #pragma unroll
            for (int o = 16; o; o >>= 1) s += __shfl_xor_sync(0xFFFFFFFFu, s, o);
            float inv = 1.0f / fmaxf(sqrtf(s), 1e-12f);
            ((float2*)(out + (size_t)warp * D))[lane] = make_float2(v.x * inv, v.y * inv);
        }
        if (gtid < NSCANMAX) g_scanstat[gtid] = 0;
        if (gtid == 0) g_ticket = 0;
    } else {
        int is32 = detect_is32(w32, twoE, &sh_is32);
        if (is32 && threadIdx.x == 0) g_is64 = 0;      // publish for k_place
        int i = (b - NB) * blockDim.x + threadIdx.x;   // logical entry index
        if (i < twoE) {
            int u = is32 ? w32[i] : (int)((const long long*)w32)[i];
            if ((unsigned)u < (unsigned)N) atomicAdd(&g_deg[u], 1);
        }
    }
}

// ---- single-pass decoupled-lookback scan of deg; dinv = rsqrt(cnt+1); self-clean ----
__global__ void k_scan(int N) {
    __shared__ int s[1024];
    __shared__ int sh_vbid, sh_run;
    int tid = threadIdx.x;
    if (tid == 0) sh_vbid = atomicAdd(&g_ticket, 1);
    __syncthreads();
    int vbid = sh_vbid;
    int i = vbid * 1024 + tid;

    int v = 0;
    if (i < N) {
        v = g_deg[i];
        g_deg[i] = 0;                                   // ready for next replay
        g_dinv[i] = rsqrtf((float)(v + 1));             // +1 = self loop
    }
    s[tid] = v;
    __syncthreads();
    for (int off = 1; off < 1024; off <<= 1) {
        int t = (tid >= off) ? s[tid - off] : 0;
        __syncthreads();
        s[tid] += t;
        __syncthreads();
    }
    int total = s[1023];
    int ex = s[tid] - v;

    if (tid == 0) {
        if (vbid == 0) {
            atomicExch(&g_scanstat[0], (total << 2) | 2);
            sh_run = 0;
        } else {
            atomicExch(&g_scanstat[vbid], (total << 2) | 1);
            int run = 0, p = vbid - 1;
            while (true) {
                int st = atomicAdd(&g_scanstat[p], 0);
                int f = st & 3;
                if (f == 2) { run += st >> 2; break; }
                if (f == 1) { run += st >> 2; p--; }
            }
            atomicExch(&g_scanstat[vbid], ((run + total) << 2) | 2);
            sh_run = run;
        }
    }
    __syncthreads();
    if (i < N) {
        int p = sh_run + ex;
        g_ptr[i] = p;
        g_cur[i] = p;
    }
}

// ---- launch 2 (grid-split): [0,SB) y = bf16(dinv*x) ; [SB,..) place edges ----
__global__ void k_place(const void* __restrict__ ei, const float* __restrict__ x,
                        int E, int N, int SB) {
    int b = blockIdx.x;
    if (b < SB) {
        int row  = b * 32 + (threadIdx.x >> 3);
        int lane = threadIdx.x & 7;
        if (row >= N) return;
        float di = g_dinv[row];
        const float4* xr = (const float4*)(x + (size_t)row * D + lane * 8);
        float4 v0 = xr[0], v1 = xr[1];
        __nv_bfloat162 o0 = __floats2bfloat162_rn(di * v0.x, di * v0.y);
        __nv_bfloat162 o1 = __floats2bfloat162_rn(di * v0.z, di * v0.w);
        __nv_bfloat162 o2 = __floats2bfloat162_rn(di * v1.x, di * v1.y);
        __nv_bfloat162 o3 = __floats2bfloat162_rn(di * v1.z, di * v1.w);
        *(uint4*)(g_b + (size_t)row * D + lane * 8) =
            make_uint4(*(unsigned*)&o0, *(unsigned*)&o1, *(unsigned*)&o2, *(unsigned*)&o3);
    } else {
        int e = (b - SB) * 256 + threadIdx.x;
        if (e >= E) return;
        int u = get_idx(ei, e);
        int v = get_idx(ei, E + e);
        if ((unsigned)u >= (unsigned)N || (unsigned)v >= (unsigned)N) return;
        int p = atomicAdd(&g_cur[v], 1);
        if ((unsigned)p < 2u * EMAX) g_src[p] = u;
        int q = atomicAdd(&g_cur[u], 1);
        if ((unsigned)q < 2u * EMAX) g_src[q] = v;
    }
}

// ---- aggregation: a[v] = dinv[v] * ( y[v] + sum_u y[u] ) ----
// bf16 rows (128B), 8 lanes/node; shift/mask unpack feeding packed f32x2 adds.
// Per edge-group: 1 LDG.128 + 4 SHF + 4 LOP3 + 4 add2.
__global__ void k_gather(int N) {
    const __nv_bfloat16* __restrict__ in = g_b;
    int node = blockIdx.x * 32 + (threadIdx.x >> 3);
    int lane = threadIdx.x & 7;
    if (node >= N) return;

    uint4 sv = ((const uint4*)(in + (size_t)node * D))[lane];   // y[v] (self)
    u64 a0 = bf2f2(sv.x), a1 = bf2f2(sv.y), a2 = bf2f2(sv.z), a3 = bf2f2(sv.w);

    int s0  = g_ptr[node];
    int cnt = g_cur[node] - s0;

    int t = 0;
    for (; t + 4 <= cnt; t += 4) {
        int s[4];
        #pragma unroll
        for (int j = 0; j < 4; j++) s[j] = g_src[s0 + t + j];
        uint4 h[4];
        #pragma unroll
        for (int j = 0; j < 4; j++)
            h[j] = ((const uint4*)(in + (size_t)s[j] * D))[lane];
        #pragma unroll
        for (int j = 0; j < 4; j++) {
            a0 = add2(a0, bf2f2(h[j].x));
            a1 = add2(a1, bf2f2(h[j].y));
            a2 = add2(a2, bf2f2(h[j].z));
            a3 = add2(a3, bf2f2(h[j].w));
        }
    }
    for (; t < cnt; t++) {
        int ss = g_src[s0 + t];
        uint4 h = ((const uint4*)(in + (size_t)ss * D))[lane];
        a0 = add2(a0, bf2f2(h.x));
        a1 = add2(a1, bf2f2(h.y));
        a2 = add2(a2, bf2f2(h.z));
        a3 = add2(a3, bf2f2(h.w));
    }

    float di = g_dinv[node];
    u64 dd = pk2(di, di);
    ulonglong2* o = (ulonglong2*)(g_a + (size_t)node * D + lane * 8);
    ulonglong2 o0; o0.x = mul2(a0, dd); o0.y = mul2(a1, dd);
    ulonglong2 o1; o1.x = mul2(a2, dd); o1.y = mul2(a3, dd);
    o[0] = o0; o[1] = o1;
}

// ---- GEMM 1 (f32x2): x1 = leaky(a W1^T + b1); out += x1; g_b = bf16(dinv*x1) ----
__global__ void k_gemm1(const float* __restrict__ W, const float* __restrict__ b,
                        float* __restrict__ out, int N) {
    __shared__ __align__(16) float s_in[64 * 64];
    __shared__ __align__(16) float s_wt[64 * 64];  // s_wt[k*64+j] = W[j*64+k]

    int tid  = threadIdx.x;
    int base = blockIdx.x * 64;

    const float4* in4  = (const float4*)(g_a + (size_t)base * D);
    float4*       sin4 = (float4*)s_in;
    #pragma unroll
    for (int r = 0; r < 4; r++) {
        int idx4 = tid + 256 * r;
        int row  = idx4 >> 4;
        sin4[idx4] = (base + row < N) ? in4[idx4] : make_float4(0.f,0.f,0.f,0.f);
    }
    #pragma unroll
    for (int r = 0; r < 16; r++) {
        int idx = tid + 256 * r;
        s_wt[(idx >> 6) * 64 + (idx & 63)] = W[(idx & 63) * 64 + (idx >> 6)];
    }
    __syncthreads();

    int ng = tid >> 4, cg = tid & 15;
    int r0 = ng * 4;
    u64 acc[4][2] = {{0,0},{0,0},{0,0},{0,0}};
    const ulonglong2* wt2 = (const ulonglong2*)s_wt;
    #pragma unroll
    for (int k = 0; k < 64; k++) {
        ulonglong2 wv = wt2[k * 16 + cg];
        #pragma unroll
        for (int r = 0; r < 4; r++) {
            float x = s_in[(r0 + r) * 64 + k];
            u64 xx = pk2(x, x);
            acc[r][0] = fma2(xx, wv.x, acc[r][0]);
            acc[r][1] = fma2(xx, wv.y, acc[r][1]);
        }
    }

    float4 bb = ((const float4*)b)[cg];
    #pragma unroll
    for (int r = 0; r < 4; r++) {
        int row = base + r0 + r;
        if (row >= N) break;
        float2 c01 = up2(acc[r][0]);
        float2 c23 = up2(acc[r][1]);
        float4 v = make_float4(c01.x + bb.x, c01.y + bb.y, c23.x + bb.z, c23.y + bb.w);
        v.x = v.x > 0.f ? v.x : 0.01f*v.x; v.y = v.y > 0.f ? v.y : 0.01f*v.y;
        v.z = v.z > 0.f ? v.z : 0.01f*v.z; v.w = v.w > 0.f ? v.w : 0.01f*v.w;
        float di = g_dinv[row];
        __nv_bfloat162* bo = (__nv_bfloat162*)(g_b + (size_t)row * D + cg * 4);
        bo[0] = __floats2bfloat162_rn(di * v.x, di * v.y);
        bo[1] = __floats2bfloat162_rn(di * v.z, di * v.w);
        size_t o = (size_t)row * 16 + cg;
        float4 ov = ((const float4*)out)[o];     // holds x
        ov.x += v.x; ov.y += v.y; ov.z += v.z; ov.w += v.w;
        ((float4*)out)[o] = ov;
    }
}

// ---- GEMM 2+3 fused (f32x2): out += leaky(a W2^T + b2) + (a W3^T + b3) ----
__global__ void k_gemm23(const float* __restrict__ W2, const float* __restrict__ b2,
                         const float* __restrict__ W3, const float* __restrict__ b3,
                         float* __restrict__ out, int N) {
    __shared__ __align__(16) float s_in[64 * 64];
    __shared__ __align__(16) float s_w2[64 * 64];
    __shared__ __align__(16) float s_w3[64 * 64];

    int tid  = threadIdx.x;
    int base = blockIdx.x * 64;

    const float4* in4  = (const float4*)(g_a + (size_t)base * D);
    float4*       sin4 = (float4*)s_in;
    #pragma unroll
    for (int r = 0; r < 4; r++) {
        int idx4 = tid + 256 * r;
        int row  = idx4 >> 4;
        sin4[idx4] = (base + row < N) ? in4[idx4] : make_float4(0.f,0.f,0.f,0.f);
    }
    #pragma unroll
    for (int r = 0; r < 16; r++) {
        int idx = tid + 256 * r;
        int j = idx & 63, k = idx >> 6;
        s_w2[k * 64 + j] = W2[j * 64 + k];
        s_w3[k * 64 + j] = W3[j * 64 + k];
    }
    __syncthreads();

    int ng = tid >> 4, cg = tid & 15;
    int r0 = ng * 4;
    u64 p[4][2] = {{0,0},{0,0},{0,0},{0,0}};
    u64 q[4][2] = {{0,0},{0,0},{0,0},{0,0}};
    const ulonglong2* w22 = (const ulonglong2*)s_w2;
    const ulonglong2* w32 = (const ulonglong2*)s_w3;
    #pragma unroll
    for (int k = 0; k < 64; k++) {
        ulonglong2 u2 = w22[k * 16 + cg];
        ulonglong2 v2 = w32[k * 16 + cg];
        #pragma unroll
        for (int r = 0; r < 4; r++) {
            float x = s_in[(r0 + r) * 64 + k];
            u64 xx = pk2(x, x);
            p[r][0] = fma2(xx, u2.x, p[r][0]);
            p[r][1] = fma2(xx, u2.y, p[r][1]);
            q[r][0] = fma2(xx, v2.x, q[r][0]);
            q[r][1] = fma2(xx, v2.y, q[r][1]);
        }
    }

    float4 bb2 = ((const float4*)b2)[cg];
    float4 bb3 = ((const float4*)b3)[cg];
    #pragma unroll
    for (int r = 0; r < 4; r++) {
        int row = base + r0 + r;
        if (row >= N) break;
        float2 p01 = up2(p[r][0]), p23 = up2(p[r][1]);
        float2 q01 = up2(q[r][0]), q23 = up2(q[r][1]);
        float4 pv = make_float4(p01.x + bb2.x, p01.y + bb2.y, p23.x + bb2.z, p23.y + bb2.w);
        pv.x = pv.x > 0.f ? pv.x : 0.01f*pv.x; pv.y = pv.y > 0.f ? pv.y : 0.01f*pv.y;
        pv.z = pv.z > 0.f ? pv.z : 0.01f*pv.z; pv.w = pv.w > 0.f ? pv.w : 0.01f*pv.w;
        float4 qv = make_float4(q01.x + bb3.x, q01.y + bb3.y, q23.x + bb3.z, q23.y + bb3.w);
        size_t o = (size_t)row * 16 + cg;
        float4 ov = ((const float4*)out)[o];     // holds x + x1
        ov.x += pv.x + qv.x;
        ov.y += pv.y + qv.y;
        ov.z += pv.z + qv.z;
        ov.w += pv.w + qv.w;
        ((float4*)out)[o] = ov;
    }
}

// ---------------- launch ----------------
extern "C" void kernel_launch(void* const* d_in, const int* in_sizes, int n_in,
                              void* d_out, int out_size) {
    const void*  ei  = d_in[0];
    const float* emb = (const float*)d_in[1];
    const float* W1 = (const float*)d_in[2];
    const float* b1 = (const float*)d_in[3];
    const float* W2 = (const float*)d_in[4];
    const float* b2 = (const float*)d_in[5];
    const float* W3 = (const float*)d_in[6];
    const float* b3 = (const float*)d_in[7];
    float* out = (float*)d_out;

    int E = in_sizes[0] / 2;
    int N = in_sizes[1] / D;

    int NB = (N * 32 + 255) / 256;                // normalize blocks (warp/node)
    int CB = (2 * E + 255) / 256;                 // count blocks
    k_prepcount<<<NB + CB, 256>>>(emb, (const int*)ei, out, N, 2 * E, NB);

    int B = (N + 1023) / 1024;
    k_scan<<<B, 1024>>>(N);

    int SB = (N + 31) / 32;                       // scale blocks (32 rows / block)
    int PB = (E + 255) / 256;                     // place blocks
    k_place<<<SB + PB, 256>>>(ei, out, E, N, SB);

    int gb = (N + 63) / 64;   // gemm blocks
    int hb = (N + 31) / 32;   // gather blocks (32 nodes / 256-thread block)

    k_gather<<<hb, 256>>>(N);   // launch index 3 — ncu samples this
    k_gemm1 <<<gb, 256>>>(W1, b1, out, N);
    k_gather<<<hb, 256>>>(N);
    k_gemm23<<<gb, 256>>>(W2, b2, W3, b3, out, N);
}

// round 14
// speedup vs baseline: 1.1359x; 1.0317x over previous
#include <cuda_runtime.h>
#include <cuda_bf16.h>
#include <stdint.h>

#define NMAX 100000
#define EMAX 1000000
#define D 64
#define NSCANMAX 128   // >= ceil(NMAX/1024)

typedef unsigned long long u64;

// ---------------- scratch (device globals; ~35 MB) ----------------
__device__ __align__(16) __nv_bfloat16 g_b0[NMAX * D]; // bf16 dinv*x
__device__ __align__(16) __nv_bfloat16 g_b1[NMAX * D]; // bf16 dinv*x1
__device__ float g_dinv[NMAX];
__device__ int   g_deg [NMAX];        // statically 0; k_scan re-zeroes after reading
__device__ int   g_ptr [NMAX];
__device__ int   g_cur [NMAX];
__device__ int   g_src [2 * EMAX];    // CSR: src node only (weights folded into y)
__device__ int   g_scanstat[NSCANMAX];
__device__ int   g_ticket;
// Static init = 1 (int64 assumed). Only ever cleared (idempotent across replays).
__device__ int   g_is64 = 1;

// ---------------- f32x2 packed helpers ----------------
__device__ __forceinline__ u64 pk2(float a, float b) {
    u64 r; asm("mov.b64 %0, {%1, %2};" : "=l"(r) : "f"(a), "f"(b)); return r;
}
__device__ __forceinline__ u64 fma2(u64 a, u64 b, u64 c) {
    u64 d; asm("fma.rn.f32x2 %0, %1, %2, %3;" : "=l"(d) : "l"(a), "l"(b), "l"(c)); return d;
}
__device__ __forceinline__ u64 add2(u64 a, u64 b) {
    u64 d; asm("add.rn.f32x2 %0, %1, %2;" : "=l"(d) : "l"(a), "l"(b)); return d;
}
__device__ __forceinline__ u64 mul2(u64 a, u64 b) {
    u64 d; asm("mul.rn.f32x2 %0, %1, %2;" : "=l"(d) : "l"(a), "l"(b)); return d;
}
__device__ __forceinline__ float2 up2(u64 a) {
    float2 f; asm("mov.b64 {%0, %1}, %2;" : "=f"(f.x), "=f"(f.y) : "l"(a)); return f;
}
// bf16x2 word -> packed f32x2 (exact): lo = w<<16, hi = w & 0xFFFF0000
__device__ __forceinline__ u64 bf2f2(unsigned w) {
    unsigned lo = w << 16;
    unsigned hi = w & 0xFFFF0000u;
    u64 r; asm("mov.b64 %0, {%1, %2};" : "=l"(r) : "r"(lo), "r"(hi));
    return r;
}

__device__ __forceinline__ int get_idx(const void* ei, int i) {
    if (g_is64) return (int)((const long long*)ei)[i];
    return ((const int*)ei)[i];
}

// Bounded dtype sniff: odd 32-bit words of the first min(256, half) logical entries
// (words < 512: in-bounds under BOTH layouts). int64 high words are 0 for node ids.
__device__ __forceinline__ int detect_is32(const int* __restrict__ w32, int twoE,
                                           int* sh_flag) {
    if (threadIdx.x == 0) *sh_flag = 0;
    __syncthreads();
    int lim = twoE >> 1; if (lim > 256) lim = 256;
    if ((int)threadIdx.x < lim && w32[2 * threadIdx.x + 1] != 0) *sh_flag = 1;
    __syncthreads();
    return *sh_flag;
}

// ---- launch 0 (grid-split): [0,NB) normalize x -> out ; [NB,..) degree count ----
__global__ void k_prepcount(const float* __restrict__ emb, const int* __restrict__ w32,
                            float* __restrict__ out, int N, int twoE, int NB) {
    __shared__ int sh_is32;
    int b = blockIdx.x;
    if (b < NB) {
        int gtid = b * blockDim.x + threadIdx.x;
        int warp = gtid >> 5, lane = gtid & 31;
        if (warp < N) {
            float2 v = ((const float2*)(emb + (size_t)warp * D))[lane];
            float s = v.x * v.x + v.y * v.y;
            #pragma unroll
            for (int o = 16; o; o >>= 1) s += __shfl_xor_sync(0xFFFFFFFFu, s, o);
            float inv = 1.0f / fmaxf(sqrtf(s), 1e-12f);
            ((float2*)(out + (size_t)warp * D))[lane] = make_float2(v.x * inv, v.y * inv);
        }
        if (gtid < NSCANMAX) g_scanstat[gtid] = 0;
        if (gtid == 0) g_ticket = 0;
    } else {
        int is32 = detect_is32(w32, twoE, &sh_is32);
        if (is32 && threadIdx.x == 0) g_is64 = 0;      // publish for k_place
        int i = (b - NB) * blockDim.x + threadIdx.x;   // logical entry index
        if (i < twoE) {
            int u = is32 ? w32[i] : (int)((const long long*)w32)[i];
            if ((unsigned)u < (unsigned)N) atomicAdd(&g_deg[u], 1);
        }
    }
}

// ---- single-pass decoupled-lookback scan of deg; dinv = rsqrt(cnt+1); self-clean ----
__global__ void k_scan(int N) {
    __shared__ int s[1024];
    __shared__ int sh_vbid, sh_run;
    int tid = threadIdx.x;
    if (tid == 0) sh_vbid = atomicAdd(&g_ticket, 1);
    __syncthreads();
    int vbid = sh_vbid;
    int i = vbid * 1024 + tid;

    int v = 0;
    if (i < N) {
        v = g_deg[i];
        g_deg[i] = 0;                                   // ready for next replay
        g_dinv[i] = rsqrtf((float)(v + 1));             // +1 = self loop
    }
    s[tid] = v;
    __syncthreads();
    for (int off = 1; off < 1024; off <<= 1) {
        int t = (tid >= off) ? s[tid - off] : 0;
        __syncthreads();
        s[tid] += t;
        __syncthreads();
    }
    int total = s[1023];
    int ex = s[tid] - v;

    if (tid == 0) {
        if (vbid == 0) {
            atomicExch(&g_scanstat[0], (total << 2) | 2);
            sh_run = 0;
        } else {
            atomicExch(&g_scanstat[vbid], (total << 2) | 1);
            int run = 0, p = vbid - 1;
            while (true) {
                int st = atomicAdd(&g_scanstat[p], 0);
                int f = st & 3;
                if (f == 2) { run += st >> 2; break; }
                if (f == 1) { run += st >> 2; p--; }
            }
            atomicExch(&g_scanstat[vbid], ((run + total) << 2) | 2);
            sh_run = run;
        }
    }
    __syncthreads();
    if (i < N) {
        int p = sh_run + ex;
        g_ptr[i] = p;
        g_cur[i] = p;
    }
}

// ---- launch 2 (grid-split): [0,SB) g_b0 = bf16(dinv*x) ; [SB,..) place edges ----
__global__ void k_place(const void* __restrict__ ei, const float* __restrict__ x,
                        int E, int N, int SB) {
    int b = blockIdx.x;
    if (b < SB) {
        int row  = b * 32 + (threadIdx.x >> 3);
        int lane = threadIdx.x & 7;
        if (row >= N) return;
        float di = g_dinv[row];
        const float4* xr = (const float4*)(x + (size_t)row * D + lane * 8);
        float4 v0 = xr[0], v1 = xr[1];
        __nv_bfloat162 o0 = __floats2bfloat162_rn(di * v0.x, di * v0.y);
        __nv_bfloat162 o1 = __floats2bfloat162_rn(di * v0.z, di * v0.w);
        __nv_bfloat162 o2 = __floats2bfloat162_rn(di * v1.x, di * v1.y);
        __nv_bfloat162 o3 = __floats2bfloat162_rn(di * v1.z, di * v1.w);
        *(uint4*)(g_b0 + (size_t)row * D + lane * 8) =
            make_uint4(*(unsigned*)&o0, *(unsigned*)&o1, *(unsigned*)&o2, *(unsigned*)&o3);
    } else {
        int e = (b - SB) * 256 + threadIdx.x;
        if (e >= E) return;
        int u = get_idx(ei, e);
        int v = get_idx(ei, E + e);
        if ((unsigned)u >= (unsigned)N || (unsigned)v >= (unsigned)N) return;
        int p = atomicAdd(&g_cur[v], 1);
        if ((unsigned)p < 2u * EMAX) g_src[p] = u;
        int q = atomicAdd(&g_cur[u], 1);
        if ((unsigned)q < 2u * EMAX) g_src[q] = v;
    }
}

// ---- gather a 64-node tile into smem: s_in[slot][k] = dinv*(y[v] + sum y[u]) ----
// 256 threads = 32 node-slots x 8 lanes, 2 sequential batches.
__device__ __forceinline__ void gather_tile(const __nv_bfloat16* __restrict__ in,
                                            float* __restrict__ s_in,
                                            int base, int N) {
    int tid = threadIdx.x;
    #pragma unroll
    for (int bat = 0; bat < 2; bat++) {
        int slot = bat * 32 + (tid >> 3);
        int node = base + slot;
        int lane = tid & 7;
        float* srow = s_in + slot * 64 + lane * 8;
        if (node < N) {
            uint4 sv = ((const uint4*)(in + (size_t)node * D))[lane];   // y[v]
            u64 a0 = bf2f2(sv.x), a1 = bf2f2(sv.y), a2 = bf2f2(sv.z), a3 = bf2f2(sv.w);
            int s0  = g_ptr[node];
            int cnt = g_cur[node] - s0;
            int t = 0;
            for (; t + 4 <= cnt; t += 4) {
                int s[4];
                #pragma unroll
                for (int j = 0; j < 4; j++) s[j] = g_src[s0 + t + j];
                uint4 h[4];
                #pragma unroll
                for (int j = 0; j < 4; j++)
                    h[j] = ((const uint4*)(in + (size_t)s[j] * D))[lane];
                #pragma unroll
                for (int j = 0; j < 4; j++) {
                    a0 = add2(a0, bf2f2(h[j].x));
                    a1 = add2(a1, bf2f2(h[j].y));
                    a2 = add2(a2, bf2f2(h[j].z));
                    a3 = add2(a3, bf2f2(h[j].w));
                }
            }
            for (; t < cnt; t++) {
                int ss = g_src[s0 + t];
                uint4 h = ((const uint4*)(in + (size_t)ss * D))[lane];
                a0 = add2(a0, bf2f2(h.x));
                a1 = add2(a1, bf2f2(h.y));
                a2 = add2(a2, bf2f2(h.z));
                a3 = add2(a3, bf2f2(h.w));
            }
            float di = g_dinv[node];
            u64 dd = pk2(di, di);
            a0 = mul2(a0, dd); a1 = mul2(a1, dd);
            a2 = mul2(a2, dd); a3 = mul2(a3, dd);
            float2 f;
            f = up2(a0); srow[0] = f.x; srow[1] = f.y;
            f = up2(a1); srow[2] = f.x; srow[3] = f.y;
            f = up2(a2); srow[4] = f.x; srow[5] = f.y;
            f = up2(a3); srow[6] = f.x; srow[7] = f.y;
        } else {
            #pragma unroll
            for (int i = 0; i < 8; i++) srow[i] = 0.f;
        }
    }
}

// ---- fused layer 1: a = Agg(y0); x1 = leaky(a W1^T + b1); out += x1; g_b1 = bf16(dinv*x1) ----
__global__ void k_gg1(const float* __restrict__ W, const float* __restrict__ b,
                      float* __restrict__ out, int N) {
    __shared__ __align__(16) float s_in[64 * 64];
    __shared__ __align__(16) float s_wt[64 * 64];  // s_wt[k*64+j] = W[j*64+k]

    int tid  = threadIdx.x;
    int base = blockIdx.x * 64;

    #pragma unroll
    for (int r = 0; r < 16; r++) {
        int idx = tid + 256 * r;
        s_wt[(idx >> 6) * 64 + (idx & 63)] = W[(idx & 63) * 64 + (idx >> 6)];
    }
    gather_tile(g_b0, s_in, base, N);
    __syncthreads();

    int ng = tid >> 4, cg = tid & 15;
    int r0 = ng * 4;
    u64 acc[4][2] = {{0,0},{0,0},{0,0},{0,0}};
    const ulonglong2* wt2 = (const ulonglong2*)s_wt;
    #pragma unroll
    for (int k = 0; k < 64; k++) {
        ulonglong2 wv = wt2[k * 16 + cg];
        #pragma unroll
        for (int r = 0; r < 4; r++) {
            float x = s_in[(r0 + r) * 64 + k];
            u64 xx = pk2(x, x);
            acc[r][0] = fma2(xx, wv.x, acc[r][0]);
            acc[r][1] = fma2(xx, wv.y, acc[r][1]);
        }
    }

    float4 bb = ((const float4*)b)[cg];
    #pragma unroll
    for (int r = 0; r < 4; r++) {
        int row = base + r0 + r;
        if (row >= N) break;
        float2 c01 = up2(acc[r][0]);
        float2 c23 = up2(acc[r][1]);
        float4 v = make_float4(c01.x + bb.x, c01.y + bb.y, c23.x + bb.z, c23.y + bb.w);
        v.x = v.x > 0.f ? v.x : 0.01f*v.x; v.y = v.y > 0.f ? v.y : 0.01f*v.y;
        v.z = v.z > 0.f ? v.z : 0.01f*v.z; v.w = v.w > 0.f ? v.w : 0.01f*v.w;
        float di = g_dinv[row];
        __nv_bfloat162* bo = (__nv_bfloat162*)(g_b1 + (size_t)row * D + cg * 4);
        bo[0] = __floats2bfloat162_rn(di * v.x, di * v.y);
        bo[1] = __floats2bfloat162_rn(di * v.z, di * v.w);
        size_t o = (size_t)row * 16 + cg;
        float4 ov = ((const float4*)out)[o];     // holds x
        ov.x += v.x; ov.y += v.y; ov.z += v.z; ov.w += v.w;
        ((float4*)out)[o] = ov;
    }
}

// ---- fused layers 2+3: a = Agg(y1); out += leaky(a W2^T + b2) + (a W3^T + b3) ----
__global__ void k_gg23(const float* __restrict__ W2, const float* __restrict__ b2,
                       const float* __restrict__ W3, const float* __restrict__ b3,
                       float* __restrict__ out, int N) {
    __shared__ __align__(16) float s_in[64 * 64];
    __shared__ __align__(16) float s_w2[64 * 64];
    __shared__ __align__(16) float s_w3[64 * 64];

    int tid  = threadIdx.x;
    int base = blockIdx.x * 64;

    #pragma unroll
    for (int r = 0; r < 16; r++) {
        int idx = tid + 256 * r;
        int j = idx & 63, k = idx >> 6;
        s_w2[k * 64 + j] = W2[j * 64 + k];
        s_w3[k * 64 + j] = W3[j * 64 + k];
    }
    gather_tile(g_b1, s_in, base, N);
    __syncthreads();

    int ng = tid >> 4, cg = tid & 15;
    int r0 = ng * 4;
    u64 p[4][2] = {{0,0},{0,0},{0,0},{0,0}};
    u64 q[4][2] = {{0,0},{0,0},{0,0},{0,0}};
    const ulonglong2* w22 = (const ulonglong2*)s_w2;
    const ulonglong2* w32 = (const ulonglong2*)s_w3;
    #pragma unroll
    for (int k = 0; k < 64; k++) {
        ulonglong2 u2 = w22[k * 16 + cg];
        ulonglong2 v2 = w32[k * 16 + cg];
        #pragma unroll
        for (int r = 0; r < 4; r++) {
            float x = s_in[(r0 + r) * 64 + k];
            u64 xx = pk2(x, x);
            p[r][0] = fma2(xx, u2.x, p[r][0]);
            p[r][1] = fma2(xx, u2.y, p[r][1]);
            q[r][0] = fma2(xx, v2.x, q[r][0]);
            q[r][1] = fma2(xx, v2.y, q[r][1]);
        }
    }

    float4 bb2 = ((const float4*)b2)[cg];
    float4 bb3 = ((const float4*)b3)[cg];
    #pragma unroll
    for (int r = 0; r < 4; r++) {
        int row = base + r0 + r;
        if (row >= N) break;
        float2 p01 = up2(p[r][0]), p23 = up2(p[r][1]);
        float2 q01 = up2(q[r][0]), q23 = up2(q[r][1]);
        float4 pv = make_float4(p01.x + bb2.x, p01.y + bb2.y, p23.x + bb2.z, p23.y + bb2.w);
        pv.x = pv.x > 0.f ? pv.x : 0.01f*pv.x; pv.y = pv.y > 0.f ? pv.y : 0.01f*pv.y;
        pv.z = pv.z > 0.f ? pv.z : 0.01f*pv.z; pv.w = pv.w > 0.f ? pv.w : 0.01f*pv.w;
        float4 qv = make_float4(q01.x + bb3.x, q01.y + bb3.y, q23.x + bb3.z, q23.y + bb3.w);
        size_t o = (size_t)row * 16 + cg;
        float4 ov = ((const float4*)out)[o];     // holds x + x1
        ov.x += pv.x + qv.x;
        ov.y += pv.y + qv.y;
        ov.z += pv.z + qv.z;
        ov.w += pv.w + qv.w;
        ((float4*)out)[o] = ov;
    }
}

// ---------------- launch ----------------
extern "C" void kernel_launch(void* const* d_in, const int* in_sizes, int n_in,
                              void* d_out, int out_size) {
    const void*  ei  = d_in[0];
    const float* emb = (const float*)d_in[1];
    const float* W1 = (const float*)d_in[2];
    const float* b1 = (const float*)d_in[3];
    const float* W2 = (const float*)d_in[4];
    const float* b2 = (const float*)d_in[5];
    const float* W3 = (const float*)d_in[6];
    const float* b3 = (const float*)d_in[7];
    float* out = (float*)d_out;

    int E = in_sizes[0] / 2;
    int N = in_sizes[1] / D;

    int NB = (N * 32 + 255) / 256;                // normalize blocks (warp/node)
    int CB = (2 * E + 255) / 256;                 // count blocks
    k_prepcount<<<NB + CB, 256>>>(emb, (const int*)ei, out, N, 2 * E, NB);

    int B = (N + 1023) / 1024;
    k_scan<<<B, 1024>>>(N);

    int SB = (N + 31) / 32;                       // scale blocks (32 rows / block)
    int PB = (E + 255) / 256;                     // place blocks
    k_place<<<SB + PB, 256>>>(ei, out, E, N, SB);

    int gb = (N + 63) / 64;                       // fused gather+gemm blocks
    k_gg1 <<<gb, 256>>>(W1, b1, out, N);
    k_gg23<<<gb, 256>>>(W2, b2, W3, b3, out, N);
}